// round 1
// baseline (speedup 1.0000x reference)
#include <cuda_runtime.h>

typedef unsigned long long ull;

#define NTHREADS 256
#define RPC 8          // rows per CTA (one row per warp)
#define NROW 2304      // 36 * 64
#define HK 36

// Packed (c,c) f32x2 coefficients: had_k[k*36+j] * (1/48)
__device__ ull g_tbl[HK * HK];

__global__ void init_tbl_kernel(const float* __restrict__ had) {
    int i = blockIdx.x * blockDim.x + threadIdx.x;
    if (i < HK * HK) {
        float c = had[i] * (1.0f / 48.0f);   // 1/sqrt(2304) = 1/48
        ull r;
        asm("mov.b64 %0, {%1, %2};" : "=l"(r) : "f"(c), "f"(c));
        g_tbl[i] = r;
    }
}

__device__ __forceinline__ ull pk2(float x, float y) {
    ull r; asm("mov.b64 %0, {%1, %2};" : "=l"(r) : "f"(x), "f"(y)); return r;
}
__device__ __forceinline__ float2 upk2(ull v) {
    float2 f; asm("mov.b64 {%0, %1}, %2;" : "=f"(f.x), "=f"(f.y) : "l"(v)); return f;
}
// packed fp32x2 fma: d = a*b + c  (per 32-bit half, IEEE rn)
__device__ __forceinline__ ull fma2(ull a, ull b, ull c) {
    ull d; asm("fma.rn.f32x2 %0, %1, %2, %3;" : "=l"(d) : "l"(a), "l"(b), "l"(c)); return d;
}

__global__ void __launch_bounds__(NTHREADS, 2)
hadamard_kernel(const float* __restrict__ x, float* __restrict__ out, int nrows) {
    __shared__ __align__(16) ull s_tbl[HK * HK];
    const int tid = threadIdx.x;
    for (int i = tid; i < HK * HK; i += NTHREADS) s_tbl[i] = g_tbl[i];
    __syncthreads();

    const int lane = tid & 31;
    const int warp = tid >> 5;
    const int row = blockIdx.x * RPC + warp;
    if (row >= nrows) return;

    const float* __restrict__ xr = x + (size_t)row * NROW;
    float* __restrict__ orow = out + (size_t)row * NROW;

    const ull ONE  = pk2(1.0f, 1.0f);
    const ull MONE = pk2(-1.0f, -1.0f);
    const ull ZERO = pk2(0.0f, 0.0f);
    // per-lane butterfly sign for each shuffle stage (bit of lane id)
    ull sg0 = (lane & 1)  ? MONE : ONE;
    ull sg1 = (lane & 2)  ? MONE : ONE;
    ull sg2 = (lane & 4)  ? MONE : ONE;
    ull sg3 = (lane & 8)  ? MONE : ONE;
    ull sg4 = (lane & 16) ? MONE : ONE;

    // ---- Phase 1: FWHT-64 per 64-element block, fully in registers ----
    // Lane l holds elements {64j+2l, 64j+2l+1}. After the transform it holds
    // t[j][m] for m = 2l, 2l+1 (natural Walsh order) — exactly what phase 2 needs.
    ull t[HK];
    #pragma unroll
    for (int j = 0; j < HK; j++) {
        float2 v = __ldg((const float2*)(xr + j * 64) + lane);
        // bit 0: local butterfly -> (lo+hi, lo-hi)
        ull tv = pk2(v.x + v.y, v.x - v.y);
        // bits 1..5: cross-lane butterflies via shfl.bfly, packed fma
        {
            float2 f = upk2(tv);
            ull w = pk2(__shfl_xor_sync(0xffffffffu, f.x, 1),
                        __shfl_xor_sync(0xffffffffu, f.y, 1));
            tv = fma2(tv, sg0, w);
        }
        {
            float2 f = upk2(tv);
            ull w = pk2(__shfl_xor_sync(0xffffffffu, f.x, 2),
                        __shfl_xor_sync(0xffffffffu, f.y, 2));
            tv = fma2(tv, sg1, w);
        }
        {
            float2 f = upk2(tv);
            ull w = pk2(__shfl_xor_sync(0xffffffffu, f.x, 4),
                        __shfl_xor_sync(0xffffffffu, f.y, 4));
            tv = fma2(tv, sg2, w);
        }
        {
            float2 f = upk2(tv);
            ull w = pk2(__shfl_xor_sync(0xffffffffu, f.x, 8),
                        __shfl_xor_sync(0xffffffffu, f.y, 8));
            tv = fma2(tv, sg3, w);
        }
        {
            float2 f = upk2(tv);
            ull w = pk2(__shfl_xor_sync(0xffffffffu, f.x, 16),
                        __shfl_xor_sync(0xffffffffu, f.y, 16));
            tv = fma2(tv, sg4, w);
        }
        t[j] = tv;
    }

    // ---- Phase 2: H36 mix across blocks: out[k*64+m] = sum_j c[k][j] * t[j][m] ----
    // Coefficients are warp-uniform LDS.128 broadcasts (2 packed coeffs per load),
    // two independent FFMA2 chains for ILP.
    for (int k = 0; k < HK; k++) {
        const ulonglong2* __restrict__ ck = (const ulonglong2*)(s_tbl + k * HK);
        ull acc0, acc1;
        {
            ulonglong2 c = ck[0];
            acc0 = fma2(t[0], c.x, ZERO);
            acc1 = fma2(t[1], c.y, ZERO);
        }
        #pragma unroll
        for (int jj = 1; jj < HK / 2; jj++) {
            ulonglong2 c = ck[jj];
            acc0 = fma2(t[2 * jj],     c.x, acc0);
            acc1 = fma2(t[2 * jj + 1], c.y, acc1);
        }
        ull acc = fma2(acc1, ONE, acc0);
        float2 r = upk2(acc);
        ((float2*)(orow + k * 64))[lane] = r;
    }
}

extern "C" void kernel_launch(void* const* d_in, const int* in_sizes, int n_in,
                              void* d_out, int out_size) {
    const float* x   = (const float*)d_in[0];
    const float* had = (const float*)d_in[1];
    float* out = (float*)d_out;
    int nrows = in_sizes[0] / NROW;   // 32768

    init_tbl_kernel<<<(HK * HK + 255) / 256, 256>>>(had);

    int grid = (nrows + RPC - 1) / RPC;
    hadamard_kernel<<<grid, NTHREADS>>>(x, out, nrows);
}

// round 2
// speedup vs baseline: 1.9681x; 1.9681x over previous
#include <cuda_runtime.h>

typedef unsigned long long ull;

#define NTHREADS 256
#define RPC 8          // rows per CTA (one row per warp)
#define NROW 2304      // 36 * 64
#define HK 36

// ---------------------------------------------------------------------------
// H36 sign masks, bit j set <=> entry (k, j) == '-'. Strings transcribed
// verbatim from the reference _H36; converted to masks at compile time.
// ---------------------------------------------------------------------------
__host__ __device__ constexpr ull rowmask(const char* s) {
    ull m = 0;
    for (int j = 0; j < 36; j++) if (s[j] == '-') m |= (1ull << j);
    return m;
}

constexpr ull RM[HK] = {
    rowmask("++++++++++++++++++-+++++++++++++++++"),
    rowmask("++++-+---++---+-+++-++-+---++---+-++"),
    rowmask("+++++-+---++---+-+++-++-+---++---+-+"),
    rowmask("++++++-+---++---+-+++-++-+---++---+-"),
    rowmask("+-+++++-+---++---++-++-++-+---++---+"),
    rowmask("++-+++++-+---++---++-++-++-+---++---"),
    rowmask("+-+-+++++-+---++--+-+-++-++-+---++--"),
    rowmask("+--+-+++++-+---++-+--+-++-++-+---++-"),
    rowmask("+---+-+++++-+---+++---+-++-++-+---++"),
    rowmask("++---+-+++++-+---+++---+-++-++-+---+"),
    rowmask("+++---+-+++++-+---+++---+-++-++-+---"),
    rowmask("+-++---+-+++++-+--+-++---+-++-++-+--"),
    rowmask("+--++---+-+++++-+-+--++---+-++-++-+-"),
    rowmask("+---++---+-+++++-++---++---+-++-++-+"),
    rowmask("++---++---+-+++++-++---++---+-++-++-"),
    rowmask("+-+---++---+-++++++-+---++---+-++-++"),
    rowmask("++-+---++---+-++++++-+---++---+-++-+"),
    rowmask("+++-+---++---+-++++++-+---++---+-++-"),
    rowmask("-+++++++++++++++++------------------"),
    rowmask("+-++-+---++---+-++----+-+++--+++-+--"),
    rowmask("++-++-+---++---+-+-----+-+++--+++-+-"),
    rowmask("+++-++-+---++---+-------+-+++--+++-+"),
    rowmask("+-++-++-+---++---+-+-----+-+++--+++-"),
    rowmask("++-++-++-+---++-----+-----+-+++--+++"),
    rowmask("+-+-++-++-+---++---+-+-----+-+++--++"),
    rowmask("+--+-++-++-+---++--++-+-----+-+++--+"),
    rowmask("+---+-++-++-+---++-+++-+-----+-+++--"),
    rowmask("++---+-++-++-+---+--+++-+-----+-+++-"),
    rowmask("+++---+-++-++-+------+++-+-----+-+++"),
    rowmask("+-++---+-++-++-+---+--+++-+-----+-++"),
    rowmask("+--++---+-++-++-+--++--+++-+-----+-+"),
    rowmask("+---++---+-++-++-+-+++--+++-+-----+-"),
    rowmask("++---++---+-++-++---+++--+++-+-----+"),
    rowmask("+-+---++---+-++-++-+-+++--+++-+-----"),
    rowmask("++-+---++---+-++-+--+-+++--+++-+----"),
    rowmask("+++-+---++---+-++----+-+++--+++-+---"),
};

// ---------------------------------------------------------------------------
// packed f32x2 helpers (sm_10x FFMA2 path, PTX-only)
// ---------------------------------------------------------------------------
__device__ __forceinline__ ull pk2(float x, float y) {
    ull r; asm("mov.b64 %0, {%1, %2};" : "=l"(r) : "f"(x), "f"(y)); return r;
}
__device__ __forceinline__ float2 upk2(ull v) {
    float2 f; asm("mov.b64 {%0, %1}, %2;" : "=f"(f.x), "=f"(f.y) : "l"(v)); return f;
}
__device__ __forceinline__ ull fma2(ull a, ull b, ull c) {
    ull d; asm("fma.rn.f32x2 %0, %1, %2, %3;" : "=l"(d) : "l"(a), "l"(b), "l"(c)); return d;
}
__device__ __forceinline__ ull add2(ull a, ull b) {
    ull d; asm("add.rn.f32x2 %0, %1, %2;" : "=l"(d) : "l"(a), "l"(b)); return d;
}
__device__ __forceinline__ ull mul2(ull a, ull b) {
    ull d; asm("mul.rn.f32x2 %0, %1, %2;" : "=l"(d) : "l"(a), "l"(b)); return d;
}

// ---------------------------------------------------------------------------
// Phase 2: out[k*64 + m] = (1/48) * sum_j sign(k,j) * t[j][m]
// Pairwise precombined: term(p) in {+P, +M, -P, -M} chosen at compile time.
// If row's first sign is '-', all term signs are flipped and scale = -1/48.
// ---------------------------------------------------------------------------
template<int K>
__device__ __forceinline__ void mix_all(const ull (&P)[HK/2], const ull (&M)[HK/2],
                                        float* __restrict__ orow, int lane,
                                        ull SC, ull NSC, ull MONE) {
    if constexpr (K < HK) {
        constexpr ull rm0  = RM[K];
        constexpr bool flip = (rm0 & 1ull) != 0;
        constexpr ull rm   = flip ? ~rm0 : rm0;   // first sign now '+'

        // pair 0: b0 == 0 by construction
        ull acc = ((rm >> 1) & 1) ? M[0] : P[0];
        #pragma unroll
        for (int p = 1; p < HK / 2; p++) {
            const int b0 = (int)((rm >> (2 * p)) & 1);
            const int b1 = (int)((rm >> (2 * p + 1)) & 1);
            const ull term = (b0 ^ b1) ? M[p] : P[p];
            if (b0) acc = fma2(term, MONE, acc);   // subtract
            else    acc = add2(acc, term);         // add
        }
        ull res = mul2(acc, flip ? NSC : SC);
        float2 r = upk2(res);
        ((float2*)(orow + K * 64))[lane] = r;
        mix_all<K + 1>(P, M, orow, lane, SC, NSC, MONE);
    }
}

__global__ void __launch_bounds__(NTHREADS, 2)
hadamard_kernel(const float* __restrict__ x, float* __restrict__ out, int nrows) {
    const int tid  = threadIdx.x;
    const int lane = tid & 31;
    const int warp = tid >> 5;
    const int row  = blockIdx.x * RPC + warp;
    if (row >= nrows) return;

    const float* __restrict__ xr = x + (size_t)row * NROW;
    float* __restrict__ orow = out + (size_t)row * NROW;

    const ull ONE  = pk2(1.0f, 1.0f);
    const ull MONE = pk2(-1.0f, -1.0f);
    const ull SC   = pk2( 1.0f / 48.0f,  1.0f / 48.0f);
    const ull NSC  = pk2(-1.0f / 48.0f, -1.0f / 48.0f);
    // per-lane butterfly signs for each shuffle stage (bit of lane id)
    ull sg0 = (lane & 1)  ? MONE : ONE;
    ull sg1 = (lane & 2)  ? MONE : ONE;
    ull sg2 = (lane & 4)  ? MONE : ONE;
    ull sg3 = (lane & 8)  ? MONE : ONE;
    ull sg4 = (lane & 16) ? MONE : ONE;

    // ---- Phase 1: FWHT-64 per 64-element block, fully in registers ----
    // Lane l holds m = {2l, 2l+1} of every block j (natural Walsh order is
    // preserved because WHT stages commute). Pairs (t[2p], t[2p+1]) are
    // immediately folded into P/M for phase 2.
    ull P[HK / 2], M[HK / 2];
    #pragma unroll
    for (int p = 0; p < HK / 2; p++) {
        ull tpair[2];
        #pragma unroll
        for (int h = 0; h < 2; h++) {
            const int j = 2 * p + h;
            float2 v = __ldg((const float2*)(xr + j * 64) + lane);
            ull tv = pk2(v.x + v.y, v.x - v.y);         // bit 0 (local)
            {
                float2 f = upk2(tv);
                ull w = pk2(__shfl_xor_sync(0xffffffffu, f.x, 1),
                            __shfl_xor_sync(0xffffffffu, f.y, 1));
                tv = fma2(tv, sg0, w);
            }
            {
                float2 f = upk2(tv);
                ull w = pk2(__shfl_xor_sync(0xffffffffu, f.x, 2),
                            __shfl_xor_sync(0xffffffffu, f.y, 2));
                tv = fma2(tv, sg1, w);
            }
            {
                float2 f = upk2(tv);
                ull w = pk2(__shfl_xor_sync(0xffffffffu, f.x, 4),
                            __shfl_xor_sync(0xffffffffu, f.y, 4));
                tv = fma2(tv, sg2, w);
            }
            {
                float2 f = upk2(tv);
                ull w = pk2(__shfl_xor_sync(0xffffffffu, f.x, 8),
                            __shfl_xor_sync(0xffffffffu, f.y, 8));
                tv = fma2(tv, sg3, w);
            }
            {
                float2 f = upk2(tv);
                ull w = pk2(__shfl_xor_sync(0xffffffffu, f.x, 16),
                            __shfl_xor_sync(0xffffffffu, f.y, 16));
                tv = fma2(tv, sg4, w);
            }
            tpair[h] = tv;
        }
        P[p] = add2(tpair[0], tpair[1]);
        M[p] = fma2(tpair[1], MONE, tpair[0]);
    }

    // ---- Phase 2: compile-time-signed H36 mix, scaled by +-1/48 ----
    mix_all<0>(P, M, orow, lane, SC, NSC, MONE);
}

extern "C" void kernel_launch(void* const* d_in, const int* in_sizes, int n_in,
                              void* d_out, int out_size) {
    const float* x = (const float*)d_in[0];
    float* out = (float*)d_out;
    int nrows = in_sizes[0] / NROW;   // 32768

    int grid = (nrows + RPC - 1) / RPC;
    hadamard_kernel<<<grid, NTHREADS>>>(x, out, nrows);
}